// round 1
// baseline (speedup 1.0000x reference)
#include <cuda_runtime.h>

#define BATCH 4
#define SEQ   4096
#define DIM   64
#define BM    128
#define BN    64
#define NEGV  10000.0f

__global__ __launch_bounds__(256, 1)
void sdpa_kernel(const float* __restrict__ Q, const float* __restrict__ K,
                 const float* __restrict__ V, const int* __restrict__ mask,
                 float* __restrict__ O) {
    __shared__ float Ks[BN][DIM];
    __shared__ float Vs[BN][DIM];
    __shared__ float pen[BN];
    __shared__ int any_one;

    const int tid = threadIdx.x;
    const int r   = tid >> 1;      // row within block (0..127)
    const int h   = tid & 1;       // which 32-wide half of D this thread owns
    const int b   = blockIdx.y;
    const int qm  = blockIdx.x * BM;
    const int q_idx = qm + r;

    const int* mb = mask + b * SEQ;

    // ---- prefix-mask check: is there any mask==1 in [0..qm]? ----
    if (tid == 0) any_one = 0;
    __syncthreads();
    for (int j = tid; j <= qm; j += 256) {
        if (mb[j]) { any_one = 1; break; }
    }
    __syncthreads();
    // If some key in the common causal prefix is unmasked, every beyond-diagonal
    // score is >= 10000 below the running max -> expf underflows to exactly 0,
    // so skipping those tiles is bit-equivalent. Otherwise do the full span
    // (additive penalties reproduce the reference exactly).
    const int n_tiles = any_one ? (qm / BN + BM / BN) : (SEQ / BN);

    // ---- load this thread's 32-float half of the query row into registers ----
    const float4* qp = reinterpret_cast<const float4*>(
        Q + ((size_t)b * SEQ + q_idx) * DIM + h * 32);
    float4 q4[8];
    #pragma unroll
    for (int i = 0; i < 8; i++) q4[i] = qp[i];

    float o[32];
    #pragma unroll
    for (int i = 0; i < 32; i++) o[i] = 0.0f;
    float m_run = -1e30f;
    float l_run = 0.0f;

    for (int t = 0; t < n_tiles; t++) {
        const int kv0 = t * BN;

        // ---- cooperative K/V tile load (coalesced float4) ----
        {
            const float4* kp = reinterpret_cast<const float4*>(K + ((size_t)b * SEQ + kv0) * DIM);
            const float4* vp = reinterpret_cast<const float4*>(V + ((size_t)b * SEQ + kv0) * DIM);
            float4* ks4 = reinterpret_cast<float4*>(&Ks[0][0]);
            float4* vs4 = reinterpret_cast<float4*>(&Vs[0][0]);
            #pragma unroll
            for (int i = 0; i < 4; i++) {
                ks4[tid + i * 256] = kp[tid + i * 256];
                vs4[tid + i * 256] = vp[tid + i * 256];
            }
            if (tid < BN) pen[tid] = mb[kv0 + tid] ? 0.0f : -NEGV;
        }
        __syncthreads();

        // ---- scores: s[j] = q . K[j] (paired threads reduce across D halves) ----
        float s[BN];
        float tile_max = -1e30f;
        #pragma unroll 4
        for (int j = 0; j < BN; j++) {
            const float4* kr = reinterpret_cast<const float4*>(&Ks[j][h * 32]);
            float acc = 0.0f;
            #pragma unroll
            for (int i = 0; i < 8; i++) {
                float4 kv = kr[i];
                acc += q4[i].x * kv.x + q4[i].y * kv.y + q4[i].z * kv.z + q4[i].w * kv.w;
            }
            acc += __shfl_xor_sync(0xffffffffu, acc, 1);
            float sc = acc * 0.125f + pen[j];           // 1/sqrt(64) = 0.125
            if (kv0 + j > q_idx) sc -= NEGV;            // additive causal penalty
            s[j] = sc;
            tile_max = fmaxf(tile_max, sc);
        }

        // ---- online softmax update ----
        const float m_new = fmaxf(m_run, tile_max);
        const float alpha = __expf(m_run - m_new);
        #pragma unroll
        for (int i = 0; i < 32; i++) o[i] *= alpha;

        float psum = 0.0f;
        #pragma unroll 2
        for (int j = 0; j < BN; j++) {
            const float p = __expf(s[j] - m_new);
            psum += p;
            const float4* vr = reinterpret_cast<const float4*>(&Vs[j][h * 32]);
            #pragma unroll
            for (int i = 0; i < 8; i++) {
                float4 vv = vr[i];
                o[i * 4 + 0] += p * vv.x;
                o[i * 4 + 1] += p * vv.y;
                o[i * 4 + 2] += p * vv.z;
                o[i * 4 + 3] += p * vv.w;
            }
        }
        l_run = l_run * alpha + psum;
        m_run = m_new;
        __syncthreads();
    }

    // ---- finalize & store ----
    const float inv = 1.0f / l_run;
    float4* op = reinterpret_cast<float4*>(O + ((size_t)b * SEQ + q_idx) * DIM + h * 32);
    #pragma unroll
    for (int i = 0; i < 8; i++) {
        op[i] = make_float4(o[i * 4 + 0] * inv, o[i * 4 + 1] * inv,
                            o[i * 4 + 2] * inv, o[i * 4 + 3] * inv);
    }
}

extern "C" void kernel_launch(void* const* d_in, const int* in_sizes, int n_in,
                              void* d_out, int out_size) {
    const float* Q    = (const float*)d_in[0];
    const float* K    = (const float*)d_in[1];
    const float* V    = (const float*)d_in[2];
    const int*   mask = (const int*)d_in[3];
    float*       O    = (float*)d_out;

    dim3 grid(SEQ / BM, BATCH);
    sdpa_kernel<<<grid, 256>>>(Q, K, V, mask, O);
}